// round 2
// baseline (speedup 1.0000x reference)
#include <cuda_runtime.h>
#include <math.h>

#define B_SZ   2048
#define T_SZ   60
#define F_SZ   89
#define H_SZ   1024
#define G4H    4096
#define OUT_SZ 30

// Scratch state (device globals — no runtime allocation).
__device__ float g_z[(size_t)B_SZ * G4H];   // 32 MB: pre-activation gates for current step
__device__ float g_h[(size_t)B_SZ * H_SZ];  // 8 MB
__device__ float g_c[(size_t)B_SZ * H_SZ];  // 8 MB

// ---------------------------------------------------------------------------
// Zero h and c at the start of every launch (graph-replay deterministic).
// ---------------------------------------------------------------------------
__global__ void init_state_kernel() {
    int idx = blockIdx.x * blockDim.x + threadIdx.x;
    if (idx < B_SZ * H_SZ) {
        g_h[idx] = 0.0f;
        g_c[idx] = 0.0f;
    }
}

// ---------------------------------------------------------------------------
// Step GEMM: z = x[:, t, :] @ W  +  h @ U  +  b     -> g_z  [B, 4H]
// 128x128 blocktile, 8x8 per-thread microtile, BK=8, 256 threads.
// ---------------------------------------------------------------------------
#define BM 128
#define BN 128
#define BK 8
#define TM 8
#define TN 8

__global__ __launch_bounds__(256) void step_gemm_kernel(
    const float* __restrict__ x,
    const float* __restrict__ W,
    const float* __restrict__ U,
    const float* __restrict__ bias,
    int t)
{
    __shared__ float As[BK][BM];
    __shared__ float Bs[BK][BN];

    const int tid    = threadIdx.x;
    const int blockM = blockIdx.y * BM;
    const int blockN = blockIdx.x * BN;
    const int tx     = tid & 15;   // 0..15
    const int ty     = tid >> 4;   // 0..15

    // A-tile load mapping: 128 rows x 8 cols, 4 consecutive K per thread
    const int aRow = tid >> 1;         // 0..127
    const int aCol = (tid & 1) * 4;    // 0 or 4
    // B-tile load mapping: 8 rows x 128 cols, 4 consecutive N per thread
    const int bRow = tid >> 5;         // 0..7
    const int bCol = (tid & 31) * 4;   // 0..124

    float acc[TM][TN];
#pragma unroll
    for (int i = 0; i < TM; i++)
#pragma unroll
        for (int j = 0; j < TN; j++) acc[i][j] = 0.0f;

    // ---------------- Part 1: x_t @ W  (K = 89, guarded) ----------------
    for (int k0 = 0; k0 < F_SZ; k0 += BK) {
        // A = x[:, t, :] ; element (m, k) at x[(m*T + t)*F + k]
#pragma unroll
        for (int i = 0; i < 4; i++) {
            int k = k0 + aCol + i;
            As[aCol + i][aRow] = (k < F_SZ)
                ? x[((size_t)(blockM + aRow) * T_SZ + t) * F_SZ + k]
                : 0.0f;
        }
        {
            int k = k0 + bRow;
            if (k < F_SZ) {
                float4 bv = *reinterpret_cast<const float4*>(
                    &W[(size_t)k * G4H + blockN + bCol]);
                Bs[bRow][bCol + 0] = bv.x;
                Bs[bRow][bCol + 1] = bv.y;
                Bs[bRow][bCol + 2] = bv.z;
                Bs[bRow][bCol + 3] = bv.w;
            } else {
                Bs[bRow][bCol + 0] = 0.0f;
                Bs[bRow][bCol + 1] = 0.0f;
                Bs[bRow][bCol + 2] = 0.0f;
                Bs[bRow][bCol + 3] = 0.0f;
            }
        }
        __syncthreads();
#pragma unroll
        for (int kk = 0; kk < BK; kk++) {
            float a[TM], b[TN];
#pragma unroll
            for (int i = 0; i < TM; i++) a[i] = As[kk][ty * TM + i];
#pragma unroll
            for (int j = 0; j < TN; j++) b[j] = Bs[kk][tx * TN + j];
#pragma unroll
            for (int i = 0; i < TM; i++)
#pragma unroll
                for (int j = 0; j < TN; j++) acc[i][j] += a[i] * b[j];
        }
        __syncthreads();
    }

    // ---------------- Part 2: h @ U  (K = 1024, unguarded) ----------------
    for (int k0 = 0; k0 < H_SZ; k0 += BK) {
        {
            float4 av = *reinterpret_cast<const float4*>(
                &g_h[(size_t)(blockM + aRow) * H_SZ + k0 + aCol]);
            As[aCol + 0][aRow] = av.x;
            As[aCol + 1][aRow] = av.y;
            As[aCol + 2][aRow] = av.z;
            As[aCol + 3][aRow] = av.w;
        }
        {
            float4 bv = *reinterpret_cast<const float4*>(
                &U[(size_t)(k0 + bRow) * G4H + blockN + bCol]);
            Bs[bRow][bCol + 0] = bv.x;
            Bs[bRow][bCol + 1] = bv.y;
            Bs[bRow][bCol + 2] = bv.z;
            Bs[bRow][bCol + 3] = bv.w;
        }
        __syncthreads();
#pragma unroll
        for (int kk = 0; kk < BK; kk++) {
            float a[TM], b[TN];
#pragma unroll
            for (int i = 0; i < TM; i++) a[i] = As[kk][ty * TM + i];
#pragma unroll
            for (int j = 0; j < TN; j++) b[j] = Bs[kk][tx * TN + j];
#pragma unroll
            for (int i = 0; i < TM; i++)
#pragma unroll
                for (int j = 0; j < TN; j++) acc[i][j] += a[i] * b[j];
        }
        __syncthreads();
    }

    // ---------------- Epilogue: add bias, write z ----------------
#pragma unroll
    for (int i = 0; i < TM; i++) {
        float* zr = &g_z[(size_t)(blockM + ty * TM + i) * G4H + blockN + tx * TN];
        const float* br = &bias[blockN + tx * TN];
#pragma unroll
        for (int j = 0; j < TN; j += 4) {
            float4 v;
            v.x = acc[i][j + 0] + br[j + 0];
            v.y = acc[i][j + 1] + br[j + 1];
            v.z = acc[i][j + 2] + br[j + 2];
            v.w = acc[i][j + 3] + br[j + 3];
            *reinterpret_cast<float4*>(&zr[j]) = v;
        }
    }
}

// ---------------------------------------------------------------------------
// Gate / state update. Keras gate order: i, f, g(candidate), o.
// c = sigmoid(f)*c + sigmoid(i)*relu(g);  h = sigmoid(o)*relu(c)
// ---------------------------------------------------------------------------
__device__ __forceinline__ float sigmoidf_(float v) {
    return 1.0f / (1.0f + expf(-v));
}

__global__ void gate_kernel() {
    int idx = blockIdx.x * blockDim.x + threadIdx.x;
    if (idx >= B_SZ * H_SZ) return;
    int m = idx >> 10;        // / H_SZ
    int j = idx & (H_SZ - 1); // % H_SZ
    const float* zr = g_z + (size_t)m * G4H;
    float zi = zr[j];
    float zf = zr[H_SZ + j];
    float zg = zr[2 * H_SZ + j];
    float zo = zr[3 * H_SZ + j];

    float ig = sigmoidf_(zi);
    float fg = sigmoidf_(zf);
    float gg = fmaxf(zg, 0.0f);
    float og = sigmoidf_(zo);

    float c = fg * g_c[idx] + ig * gg;
    g_c[idx] = c;
    g_h[idx] = og * fmaxf(c, 0.0f);
}

// ---------------------------------------------------------------------------
// Dense head: y = h_T @ Wd + bd   ([2048,1024] @ [1024,30])
// ---------------------------------------------------------------------------
__global__ void dense_kernel(const float* __restrict__ Wd,
                             const float* __restrict__ bd,
                             float* __restrict__ out)
{
    int m = blockIdx.x;
    int o = threadIdx.x;
    if (o >= OUT_SZ) return;
    const float* hr = g_h + (size_t)m * H_SZ;
    float acc = bd[o];
#pragma unroll 4
    for (int k = 0; k < H_SZ; k++)
        acc = fmaf(hr[k], Wd[(size_t)k * OUT_SZ + o], acc);
    out[(size_t)m * OUT_SZ + o] = acc;
}

// ---------------------------------------------------------------------------
extern "C" void kernel_launch(void* const* d_in, const int* in_sizes, int n_in,
                              void* d_out, int out_size)
{
    const float* x  = (const float*)d_in[0];  // [B, T, F]
    const float* W  = (const float*)d_in[1];  // [F, 4H]
    const float* U  = (const float*)d_in[2];  // [H, 4H]
    const float* b  = (const float*)d_in[3];  // [4H]
    const float* Wd = (const float*)d_in[4];  // [H, OUT]
    const float* bd = (const float*)d_in[5];  // [OUT]
    float* out = (float*)d_out;               // [B, OUT, 1]

    init_state_kernel<<<(B_SZ * H_SZ + 255) / 256, 256>>>();

    dim3 grid(G4H / BN, B_SZ / BM);  // 32 x 16 = 512 blocks
    for (int t = 0; t < T_SZ; t++) {
        step_gemm_kernel<<<grid, 256>>>(x, W, U, b, t);
        gate_kernel<<<(B_SZ * H_SZ + 255) / 256, 256>>>();
    }

    dense_kernel<<<B_SZ, 32>>>(Wd, bd, out);
}

// round 5
// speedup vs baseline: 2.1806x; 2.1806x over previous
#include <cuda_runtime.h>
#include <cuda_bf16.h>
#include <cstdint>
#include <math.h>

#define Bsz 2048
#define Tsz 60
#define Fsz 89
#define Hsz 1024
#define OUTsz 30

#define NSTG 35          // 32 k-stages of h@U + 3 of x@W (F padded to 96)
#define ROWB 144         // smem row pitch: 32 bf16 hi (64B) + 32 bf16 lo (64B) + 16B pad
#define MATB 18432       // 128 rows * 144B
#define STAGE_B 36864    // A tile + B tile
#define SMEM_TOTAL (2 * STAGE_B)

// ---------------- device globals (no runtime allocation) ----------------
__device__ __align__(16) __nv_bfloat16 g_UB_hi[(size_t)4096 * 1024];
__device__ __align__(16) __nv_bfloat16 g_UB_lo[(size_t)4096 * 1024];
__device__ __align__(16) __nv_bfloat16 g_WB_hi[(size_t)4096 * 96];
__device__ __align__(16) __nv_bfloat16 g_WB_lo[(size_t)4096 * 96];
__device__ __align__(16) __nv_bfloat16 g_xB_hi[(size_t)2048 * 60 * 96];
__device__ __align__(16) __nv_bfloat16 g_xB_lo[(size_t)2048 * 60 * 96];
__device__ __align__(16) __nv_bfloat16 g_hB_hi[2][(size_t)2048 * 1024];
__device__ __align__(16) __nv_bfloat16 g_hB_lo[2][(size_t)2048 * 1024];
__device__ float g_c[(size_t)2048 * 1024];
__device__ float g_hflat[(size_t)2048 * 1024];
__device__ float g_bil[4096];

// ---------------- PTX helpers (baseline ISA only: sm_80-level) ----------------
__device__ __forceinline__ uint32_t smem_u32(const void* p) {
    uint32_t a;
    asm("{ .reg .u64 t; cvta.to.shared.u64 t, %1; cvt.u32.u64 %0, t; }" : "=r"(a) : "l"(p));
    return a;
}
#define CP16(dst, src) \
    asm volatile("cp.async.ca.shared.global [%0], [%1], 16;" :: "r"(dst), "l"(src))
#define CPCOMMIT() asm volatile("cp.async.commit_group;" ::: "memory")
#define CPWAIT1()  asm volatile("cp.async.wait_group 1;" ::: "memory")
#define CPWAIT0()  asm volatile("cp.async.wait_group 0;" ::: "memory")

__device__ __forceinline__ void ldm4(uint32_t* r, uint32_t addr) {
    asm volatile("ldmatrix.sync.aligned.m8n8.x4.shared.b16 {%0,%1,%2,%3}, [%4];"
        : "=r"(r[0]), "=r"(r[1]), "=r"(r[2]), "=r"(r[3]) : "r"(addr));
}
__device__ __forceinline__ void mma16816(float* d, const uint32_t* a, const uint32_t* b) {
    asm volatile(
        "mma.sync.aligned.m16n8k16.row.col.f32.bf16.bf16.f32 "
        "{%0,%1,%2,%3}, {%4,%5,%6,%7}, {%8,%9}, {%0,%1,%2,%3};"
        : "+f"(d[0]), "+f"(d[1]), "+f"(d[2]), "+f"(d[3])
        : "r"(a[0]), "r"(a[1]), "r"(a[2]), "r"(a[3]), "r"(b[0]), "r"(b[1]));
}
__device__ __forceinline__ void split2(float v, __nv_bfloat16& hi, __nv_bfloat16& lo) {
    hi = __float2bfloat16(v);
    lo = __float2bfloat16(v - __bfloat162float(hi));
}

// ---------------- repack / init kernels ----------------
__global__ void k_zero() {
    size_t i = (size_t)blockIdx.x * 256 + threadIdx.x;
    if (i < (size_t)Bsz * Hsz) {
        g_c[i] = 0.0f;
        g_hB_hi[0][i] = __float2bfloat16(0.0f);
        g_hB_lo[0][i] = __float2bfloat16(0.0f);
    }
}
// U[k][c] -> [np][k], np = 4*j + gate (gate = c>>10, j = c&1023)
__global__ void k_repack_U(const float* __restrict__ U) {
    size_t i = (size_t)blockIdx.x * 256 + threadIdx.x;
    if (i >= (size_t)1024 * 4096) return;
    int k = (int)(i >> 12), c = (int)(i & 4095);
    int np = 4 * (c & 1023) + (c >> 10);
    __nv_bfloat16 hi, lo; split2(U[i], hi, lo);
    g_UB_hi[(size_t)np * 1024 + k] = hi;
    g_UB_lo[(size_t)np * 1024 + k] = lo;
}
__global__ void k_repack_W(const float* __restrict__ W) {
    size_t i = (size_t)blockIdx.x * 256 + threadIdx.x;
    if (i >= (size_t)96 * 4096) return;
    int k = (int)(i / 4096), c = (int)(i % 4096);
    float v = (k < Fsz) ? W[(size_t)k * 4096 + c] : 0.0f;
    int np = 4 * (c & 1023) + (c >> 10);
    __nv_bfloat16 hi, lo; split2(v, hi, lo);
    g_WB_hi[(size_t)np * 96 + k] = hi;
    g_WB_lo[(size_t)np * 96 + k] = lo;
}
// x[m][t][89] -> [m][t][96] (zero-padded)
__global__ void k_repack_x(const float* __restrict__ x) {
    size_t i = (size_t)blockIdx.x * 256 + threadIdx.x;
    if (i >= (size_t)Bsz * Tsz * 96) return;
    int k = (int)(i % 96);
    size_t mt_ = i / 96;  // m*60 + t
    float v = (k < Fsz) ? x[mt_ * Fsz + k] : 0.0f;
    __nv_bfloat16 hi, lo; split2(v, hi, lo);
    g_xB_hi[i] = hi;
    g_xB_lo[i] = lo;
}
__global__ void k_repack_b(const float* __restrict__ b) {
    int c = blockIdx.x * 256 + threadIdx.x;
    if (c < 4096) g_bil[4 * (c & 1023) + (c >> 10)] = b[c];
}

// ---------------- LSTM gate update ----------------
__device__ __forceinline__ void gate_update(int m, int j, float zi, float zf,
                                            float zg, float zo, int t, int dst) {
    size_t idx = (size_t)m * Hsz + j;
    float ig = 1.0f / (1.0f + expf(-zi));
    float fg = 1.0f / (1.0f + expf(-zf));
    float og = 1.0f / (1.0f + expf(-zo));
    float c = fg * g_c[idx] + ig * fmaxf(zg, 0.0f);
    g_c[idx] = c;
    float h = og * fmaxf(c, 0.0f);
    if (t == Tsz - 1) {
        g_hflat[idx] = h;
    } else {
        __nv_bfloat16 hh, hl; split2(h, hh, hl);
        g_hB_hi[dst][idx] = hh;
        g_hB_lo[dst][idx] = hl;
    }
}

// ---------------- per-timestep fused GEMM + gate kernel ----------------
// CTA tile 128(M) x 128(N-interleaved), 8 warps (2x4), warp tile 64x32.
// z = [h | x_t] @ [U ; W] + b with bf16x3 split; epilogue applies gates.
__global__ __launch_bounds__(256) void step_kernel(int t) {
    extern __shared__ __align__(128) char smem[];
    const int tid  = threadIdx.x;
    const int nt   = blockIdx.x;      // 0..31
    const int mt   = blockIdx.y;      // 0..15
    const int wid  = tid >> 5, lane = tid & 31;
    const int wm   = wid >> 2, wn = wid & 3;
    const int src  = t & 1, dst = src ^ 1;

    float acc[4][4][4];
#pragma unroll
    for (int a = 0; a < 4; a++)
#pragma unroll
        for (int b = 0; b < 4; b++)
#pragma unroll
            for (int c = 0; c < 4; c++) acc[a][b][c] = 0.0f;

    // ldmatrix per-lane addressing (A and B share the pattern; no .trans needed)
    const int lr  = (lane & 7) + ((lane >> 3) & 1) * 8;  // row within 16-row tile
    const int lkb = ((lane >> 4) & 1) * 16;              // 0 or 16 bytes (k half)

    auto issue_stage = [&](int s) {
        const __nv_bfloat16 *aH, *aL, *bH, *bL;
        int aStr, bStr; size_t aOff, bOff;
        if (s < 32) {
            aH = g_hB_hi[src]; aL = g_hB_lo[src]; aStr = 1024; aOff = (size_t)32 * s;
            bH = g_UB_hi;      bL = g_UB_lo;      bStr = 1024; bOff = (size_t)32 * s;
        } else {
            int i = s - 32;
            aH = g_xB_hi; aL = g_xB_lo; aStr = Tsz * 96; aOff = (size_t)t * 96 + 32 * i;
            bH = g_WB_hi; bL = g_WB_lo; bStr = 96;       bOff = (size_t)32 * i;
        }
        char* base = smem + (s & 1) * STAGE_B;
#pragma unroll
        for (int it = 0; it < 8; it++) {
            int q = it * 256 + tid;          // 2048 chunks of 16B
            int mat = q >> 10, rem = q & 1023;
            int row = rem >> 3, c8 = rem & 7;
            int half = c8 >> 2, kc = c8 & 3;
            const __nv_bfloat16* gp;
            if (mat == 0)
                gp = (half ? aL : aH) + (size_t)(mt * 128 + row) * aStr + aOff + kc * 8;
            else
                gp = (half ? bL : bH) + (size_t)(nt * 128 + row) * bStr + bOff + kc * 8;
            uint32_t d = smem_u32(base + mat * MATB + row * ROWB + half * 64 + kc * 16);
            CP16(d, gp);
        }
        CPCOMMIT();
    };

    auto compute_stage = [&](int buf) {
        uint32_t aBase = smem_u32(smem + buf * STAGE_B) + lr * ROWB + lkb;
        uint32_t bBase = aBase + MATB;
#pragma unroll
        for (int kk = 0; kk < 2; kk++) {
            uint32_t aHf[4][4], aLf[4][4], bHf[4][2], bLf[4][2];
#pragma unroll
            for (int im = 0; im < 4; im++) {
                uint32_t ra = aBase + (wm * 64 + im * 16) * ROWB + kk * 32;
                ldm4(aHf[im], ra);
                ldm4(aLf[im], ra + 64);
            }
#pragma unroll
            for (int ig = 0; ig < 2; ig++) {
                uint32_t rb = bBase + (wn * 32 + ig * 16) * ROWB + kk * 32;
                uint32_t r[4];
                ldm4(r, rb);
                bHf[ig * 2][0] = r[0]; bHf[ig * 2][1] = r[2];
                bHf[ig * 2 + 1][0] = r[1]; bHf[ig * 2 + 1][1] = r[3];
                ldm4(r, rb + 64);
                bLf[ig * 2][0] = r[0]; bLf[ig * 2][1] = r[2];
                bLf[ig * 2 + 1][0] = r[1]; bLf[ig * 2 + 1][1] = r[3];
            }
#pragma unroll
            for (int im = 0; im < 4; im++)
#pragma unroll
                for (int iu = 0; iu < 4; iu++) {
                    mma16816(acc[im][iu], aHf[im], bHf[iu]);  // hi*hi
                    mma16816(acc[im][iu], aHf[im], bLf[iu]);  // hi*lo
                    mma16816(acc[im][iu], aLf[im], bHf[iu]);  // lo*hi
                }
        }
    };

    issue_stage(0);
    issue_stage(1);
#pragma unroll 1
    for (int s = 0; s < NSTG; s++) {
        if (s == NSTG - 1) { CPWAIT0(); } else { CPWAIT1(); }
        __syncthreads();
        compute_stage(s & 1);
        __syncthreads();
        if (s + 2 < NSTG) issue_stage(s + 2);
    }

    // ---------------- fused gate epilogue ----------------
    const int g  = lane >> 2;
    const int t4 = lane & 3;
#pragma unroll
    for (int im = 0; im < 4; im++) {
#pragma unroll
        for (int iu = 0; iu < 4; iu++) {
            int np = nt * 128 + wn * 32 + iu * 8 + 2 * t4;
            float b0 = g_bil[np], b1 = g_bil[np + 1];
            float z0 = acc[im][iu][0] + b0;   // row g    : col np, np+1
            float z1 = acc[im][iu][1] + b1;
            float z2 = acc[im][iu][2] + b0;   // row g+8
            float z3 = acc[im][iu][3] + b1;
            // even t4 holds (i,f); odd partner holds (g,o) of the same unit
            float o0 = __shfl_xor_sync(0xFFFFFFFF, z0, 1);
            float o1 = __shfl_xor_sync(0xFFFFFFFF, z1, 1);
            float o2 = __shfl_xor_sync(0xFFFFFFFF, z2, 1);
            float o3 = __shfl_xor_sync(0xFFFFFFFF, z3, 1);
            if ((t4 & 1) == 0) {
                int j  = np >> 2;                       // hidden unit index
                int m0 = mt * 128 + wm * 64 + im * 16 + g;
                gate_update(m0,     j, z0, z1, o0, o1, t, dst);
                gate_update(m0 + 8, j, z2, z3, o2, o3, t, dst);
            }
        }
    }
}

// ---------------- dense head ----------------
__global__ void dense_kernel(const float* __restrict__ Wd,
                             const float* __restrict__ bd,
                             float* __restrict__ out) {
    int m = blockIdx.x, o = threadIdx.x;
    if (o >= OUTsz) return;
    const float* hr = g_hflat + (size_t)m * Hsz;
    float acc = bd[o];
#pragma unroll 4
    for (int k = 0; k < Hsz; k++)
        acc = fmaf(hr[k], Wd[(size_t)k * OUTsz + o], acc);
    out[(size_t)m * OUTsz + o] = acc;
}

// ---------------------------------------------------------------------------
extern "C" void kernel_launch(void* const* d_in, const int* in_sizes, int n_in,
                              void* d_out, int out_size) {
    const float* x  = (const float*)d_in[0];
    const float* W  = (const float*)d_in[1];
    const float* U  = (const float*)d_in[2];
    const float* b  = (const float*)d_in[3];
    const float* Wd = (const float*)d_in[4];
    const float* bd = (const float*)d_in[5];
    float* out = (float*)d_out;

    static int attr_set = 0;
    if (!attr_set) {
        cudaFuncSetAttribute(step_kernel, cudaFuncAttributeMaxDynamicSharedMemorySize,
                             SMEM_TOTAL);
        attr_set = 1;
    }

    k_zero<<<(Bsz * Hsz + 255) / 256, 256>>>();
    k_repack_U<<<(1024 * 4096 + 255) / 256, 256>>>(U);
    k_repack_W<<<(96 * 4096 + 255) / 256, 256>>>(W);
    k_repack_x<<<(Bsz * Tsz * 96 + 255) / 256, 256>>>(x);
    k_repack_b<<<16, 256>>>(b);

    dim3 grid(32, 16);
    for (int t = 0; t < Tsz; t++)
        step_kernel<<<grid, 256, SMEM_TOTAL>>>(t);

    dense_kernel<<<Bsz, 32>>>(Wd, bd, out);
}

// round 6
// speedup vs baseline: 4.0009x; 1.8348x over previous
#include <cuda_runtime.h>
#include <cuda_fp16.h>
#include <cstdint>
#include <math.h>

#define Bsz 2048
#define Tsz 60
#define Fsz 89
#define Hsz 1024
#define OUTsz 30

#define NSTG 35            // 32 k-stages of h@U + 3 of x@W (F padded to 96)
#define ROWB 80            // smem row pitch: 32 fp16 (64B) + 16B pad (conflict-free ldmatrix)
#define MAT_A 10240        // 128 rows * 80
#define MAT_B 20480        // 256 rows * 80
#define STAGE_B 30720
#define SMEM_TOTAL (2 * STAGE_B)

// ---------------- device globals (no runtime allocation) ----------------
__device__ __align__(16) __half g_UB[(size_t)4096 * 1024];     // [np][k], np = 4*j+gate
__device__ __align__(16) __half g_WB[(size_t)4096 * 96];       // [np][k]
__device__ __align__(16) __half g_xB[(size_t)2048 * 60 * 96];  // [m][t][96]
__device__ __align__(16) __half g_hB[2][(size_t)2048 * 1024];  // ping-pong [m][k]
__device__ float g_c[(size_t)2048 * 1024];
__device__ float g_hflat[(size_t)2048 * 1024];
__device__ float g_bil[4096];

// ---------------- PTX helpers (baseline ISA only) ----------------
__device__ __forceinline__ uint32_t smem_u32(const void* p) {
    uint32_t a;
    asm("{ .reg .u64 t; cvta.to.shared.u64 t, %1; cvt.u32.u64 %0, t; }" : "=r"(a) : "l"(p));
    return a;
}
#define CP16(dst, src) \
    asm volatile("cp.async.cg.shared.global [%0], [%1], 16;" :: "r"(dst), "l"(src))
#define CPCOMMIT() asm volatile("cp.async.commit_group;" ::: "memory")
#define CPWAIT1()  asm volatile("cp.async.wait_group 1;" ::: "memory")
#define CPWAIT0()  asm volatile("cp.async.wait_group 0;" ::: "memory")

__device__ __forceinline__ void ldm4(uint32_t* r, uint32_t addr) {
    asm volatile("ldmatrix.sync.aligned.m8n8.x4.shared.b16 {%0,%1,%2,%3}, [%4];"
        : "=r"(r[0]), "=r"(r[1]), "=r"(r[2]), "=r"(r[3]) : "r"(addr));
}
__device__ __forceinline__ void mma16816(float* d, const uint32_t* a, const uint32_t* b) {
    asm volatile(
        "mma.sync.aligned.m16n8k16.row.col.f32.f16.f16.f32 "
        "{%0,%1,%2,%3}, {%4,%5,%6,%7}, {%8,%9}, {%0,%1,%2,%3};"
        : "+f"(d[0]), "+f"(d[1]), "+f"(d[2]), "+f"(d[3])
        : "r"(a[0]), "r"(a[1]), "r"(a[2]), "r"(a[3]), "r"(b[0]), "r"(b[1]));
}

// ---------------- repack / init kernels ----------------
__global__ void k_zero() {
    size_t i = (size_t)blockIdx.x * 256 + threadIdx.x;
    if (i < (size_t)Bsz * Hsz) {
        g_c[i] = 0.0f;
        g_hB[0][i] = __float2half(0.0f);
    }
}
__global__ void k_repack_U(const float* __restrict__ U) {
    size_t i = (size_t)blockIdx.x * 256 + threadIdx.x;
    if (i >= (size_t)1024 * 4096) return;
    int k = (int)(i >> 12), c = (int)(i & 4095);
    int np = 4 * (c & 1023) + (c >> 10);
    g_UB[(size_t)np * 1024 + k] = __float2half(U[i]);
}
__global__ void k_repack_W(const float* __restrict__ W) {
    size_t i = (size_t)blockIdx.x * 256 + threadIdx.x;
    if (i >= (size_t)96 * 4096) return;
    int k = (int)(i / 4096), c = (int)(i % 4096);
    float v = (k < Fsz) ? W[(size_t)k * 4096 + c] : 0.0f;
    int np = 4 * (c & 1023) + (c >> 10);
    g_WB[(size_t)np * 96 + k] = __float2half(v);
}
__global__ void k_repack_x(const float* __restrict__ x) {
    size_t i = (size_t)blockIdx.x * 256 + threadIdx.x;
    if (i >= (size_t)Bsz * Tsz * 96) return;
    int k = (int)(i % 96);
    size_t mt_ = i / 96;
    float v = (k < Fsz) ? x[mt_ * Fsz + k] : 0.0f;
    g_xB[i] = __float2half(v);
}
__global__ void k_repack_b(const float* __restrict__ b) {
    int c = blockIdx.x * 256 + threadIdx.x;
    if (c < 4096) g_bil[4 * (c & 1023) + (c >> 10)] = b[c];
}

// ---------------- LSTM gate update ----------------
__device__ __forceinline__ void gate_update(int m, int j, float zi, float zf,
                                            float zg, float zo, int t, int dst) {
    size_t idx = (size_t)m * Hsz + j;
    float ig = 1.0f / (1.0f + expf(-zi));
    float fg = 1.0f / (1.0f + expf(-zf));
    float og = 1.0f / (1.0f + expf(-zo));
    float c = fg * g_c[idx] + ig * fmaxf(zg, 0.0f);
    g_c[idx] = c;
    float h = og * fmaxf(c, 0.0f);
    if (t == Tsz - 1) g_hflat[idx] = h;
    else              g_hB[dst][idx] = __float2half(h);
}

// ---------------- per-timestep fused GEMM + gate kernel ----------------
// CTA tile 128(M) x 256(N-interleaved), 16 warps (2x8), warp tile 64x32, fp16.
__global__ __launch_bounds__(512) void step_kernel(int t) {
    extern __shared__ __align__(128) char smem[];
    const int tid  = threadIdx.x;
    const int nt   = blockIdx.x;      // 0..15 (256 np-cols)
    const int mt   = blockIdx.y;      // 0..15 (128 rows)
    const int wid  = tid >> 5, lane = tid & 31;
    const int wm   = wid >> 3, wn = wid & 7;
    const int src  = t & 1, dst = src ^ 1;

    float acc[4][4][4];
#pragma unroll
    for (int a = 0; a < 4; a++)
#pragma unroll
        for (int b = 0; b < 4; b++)
#pragma unroll
            for (int c = 0; c < 4; c++) acc[a][b][c] = 0.0f;

    const int lr  = lane & 15;                 // row within 16-row ldmatrix tile
    const int lkb = ((lane >> 4) & 1) * 16;    // 16B k-half select

    auto issue_stage = [&](int s) {
        const __half *aP, *bP;
        int aStr, bStr; size_t aOff, bOff;
        if (s < 32) {
            aP = g_hB[src]; aStr = 1024; aOff = (size_t)32 * s;
            bP = g_UB;      bStr = 1024; bOff = (size_t)32 * s;
        } else {
            int i = s - 32;
            aP = g_xB; aStr = Tsz * 96; aOff = (size_t)t * 96 + 32 * i;
            bP = g_WB; bStr = 96;       bOff = (size_t)32 * i;
        }
        char* base = smem + (s & 1) * STAGE_B;
#pragma unroll
        for (int it = 0; it < 3; it++) {
            int q = it * 512 + tid;            // 1536 chunks of 16B
            const __half* gp;
            uint32_t d;
            if (q < 512) {
                int row = q >> 2, kc = q & 3;
                gp = aP + (size_t)(mt * 128 + row) * aStr + aOff + kc * 8;
                d = smem_u32(base + row * ROWB + kc * 16);
            } else {
                int p = q - 512;
                int row = p >> 2, kc = p & 3;
                gp = bP + (size_t)(nt * 256 + row) * bStr + bOff + kc * 8;
                d = smem_u32(base + MAT_A + row * ROWB + kc * 16);
            }
            CP16(d, gp);
        }
        CPCOMMIT();
    };

    auto compute_stage = [&](int buf) {
        uint32_t aBase = smem_u32(smem + buf * STAGE_B) + lr * ROWB + lkb;
        uint32_t bBase = aBase + MAT_A;
#pragma unroll
        for (int kk = 0; kk < 2; kk++) {
            uint32_t aF[4][4], bF[4][2];
#pragma unroll
            for (int im = 0; im < 4; im++)
                ldm4(aF[im], aBase + (wm * 64 + im * 16) * ROWB + kk * 32);
#pragma unroll
            for (int ig = 0; ig < 2; ig++) {
                uint32_t r[4];
                ldm4(r, bBase + (wn * 32 + ig * 16) * ROWB + kk * 32);
                bF[ig * 2][0] = r[0];     bF[ig * 2][1] = r[2];
                bF[ig * 2 + 1][0] = r[1]; bF[ig * 2 + 1][1] = r[3];
            }
#pragma unroll
            for (int im = 0; im < 4; im++)
#pragma unroll
                for (int iu = 0; iu < 4; iu++)
                    mma16816(acc[im][iu], aF[im], bF[iu]);
        }
    };

    issue_stage(0);
    issue_stage(1);
#pragma unroll 1
    for (int s = 0; s < NSTG; s++) {
        if (s == NSTG - 1) { CPWAIT0(); } else { CPWAIT1(); }
        __syncthreads();
        compute_stage(s & 1);
        __syncthreads();
        if (s + 2 < NSTG) issue_stage(s + 2);
    }

    // ---------------- fused gate epilogue ----------------
    const int g  = lane >> 2;
    const int t4 = lane & 3;
#pragma unroll
    for (int im = 0; im < 4; im++) {
#pragma unroll
        for (int iu = 0; iu < 4; iu++) {
            int np = nt * 256 + wn * 32 + iu * 8 + 2 * t4;
            float b0 = g_bil[np], b1 = g_bil[np + 1];
            float z0 = acc[im][iu][0] + b0;
            float z1 = acc[im][iu][1] + b1;
            float z2 = acc[im][iu][2] + b0;
            float z3 = acc[im][iu][3] + b1;
            float o0 = __shfl_xor_sync(0xFFFFFFFF, z0, 1);
            float o1 = __shfl_xor_sync(0xFFFFFFFF, z1, 1);
            float o2 = __shfl_xor_sync(0xFFFFFFFF, z2, 1);
            float o3 = __shfl_xor_sync(0xFFFFFFFF, z3, 1);
            if ((t4 & 1) == 0) {
                int j  = np >> 2;
                int m0 = mt * 128 + wm * 64 + im * 16 + g;
                gate_update(m0,     j, z0, z1, o0, o1, t, dst);
                gate_update(m0 + 8, j, z2, z3, o2, o3, t, dst);
            }
        }
    }
}

// ---------------- dense head ----------------
__global__ void dense_kernel(const float* __restrict__ Wd,
                             const float* __restrict__ bd,
                             float* __restrict__ out) {
    int m = blockIdx.x, o = threadIdx.x;
    if (o >= OUTsz) return;
    const float* hr = g_hflat + (size_t)m * Hsz;
    float acc = bd[o];
#pragma unroll 4
    for (int k = 0; k < Hsz; k++)
        acc = fmaf(hr[k], Wd[(size_t)k * OUTsz + o], acc);
    out[(size_t)m * OUTsz + o] = acc;
}

// ---------------------------------------------------------------------------
extern "C" void kernel_launch(void* const* d_in, const int* in_sizes, int n_in,
                              void* d_out, int out_size) {
    const float* x  = (const float*)d_in[0];
    const float* W  = (const float*)d_in[1];
    const float* U  = (const float*)d_in[2];
    const float* b  = (const float*)d_in[3];
    const float* Wd = (const float*)d_in[4];
    const float* bd = (const float*)d_in[5];
    float* out = (float*)d_out;

    static int attr_set = 0;
    if (!attr_set) {
        cudaFuncSetAttribute(step_kernel, cudaFuncAttributeMaxDynamicSharedMemorySize,
                             SMEM_TOTAL);
        attr_set = 1;
    }

    k_zero<<<(Bsz * Hsz + 255) / 256, 256>>>();
    k_repack_U<<<(1024 * 4096 + 255) / 256, 256>>>(U);
    k_repack_W<<<(96 * 4096 + 255) / 256, 256>>>(W);
    k_repack_x<<<(Bsz * Tsz * 96 + 255) / 256, 256>>>(x);
    k_repack_b<<<16, 256>>>(b);

    dim3 grid(16, 16);
    for (int t = 0; t < Tsz; t++)
        step_kernel<<<grid, 512, SMEM_TOTAL>>>(t);

    dense_kernel<<<Bsz, 32>>>(Wd, bd, out);
}